// round 8
// baseline (speedup 1.0000x reference)
#include <cuda_runtime.h>
#include <cstdint>
#include <cstddef>

#define B_      64
#define S_      784
#define SP_     792
#define T_      500
#define N_      512
#define TP_     522
#define KS_     21
#define THETA_  40
#define CAP_    128
#define NT_     32
#define TC_     64
#define THREADS_ 1024
#define GRID_   148
#define PSTR_   544      // u16 pot row stride (covers t<=543)
#define ZSTR_   67       // uint2 z row stride
#define NTICK_  (B_ * (N_ / NT_))     // 1024

__device__ int            g_cnt[B_ * T_];
__device__ unsigned short g_list[B_ * T_ * CAP_];   // sentinel-filled (s=784)
__device__ unsigned       g_key[B_ * TP_];
__device__ unsigned       g_oh[S_ * N_];            // one-hot weight words
__device__ unsigned       g_ticket;

__device__ __forceinline__ int dp4a_(unsigned a, unsigned b, int c) {
    int r;
    asm("dp4a.u32.u32 %0, %1, %2, %3;" : "=r"(r) : "r"(a), "r"(b), "r"(c));
    return r;
}

// ---------------------------------------------------------------------------
__global__ void fill_kernel() {
    int i = blockIdx.x * blockDim.x + threadIdx.x;
    const int L4 = B_ * T_ * CAP_ / 8;
    if (i < L4) {
        uint4 v; v.x = v.y = v.z = v.w = 0x03100310u;
        ((uint4*)g_list)[i] = v;
    }
    if (i < B_ * T_)  g_cnt[i] = 0;
    if (i < B_ * TP_) g_key[i] = 0u;
    if (i == 0)       g_ticket = 0u;
}

// One-hot weights: g_oh[s*N+n] = 1 << 4*w[n][s]. Coalesced read, scattered write.
__global__ void oh_kernel(const int* __restrict__ weight) {
    int i = blockIdx.x * blockDim.x + threadIdx.x;
    if (i >= N_ * S_) return;
    int n = i / S_, s = i - n * S_;
    g_oh[s * N_ + n] = 1u << (4 * (weight[i] & 7));
}

__global__ void prepass_kernel(const float4* __restrict__ x) {
    const int T4 = T_ / 4;
    int idx = blockIdx.x * blockDim.x + threadIdx.x;
    if (idx >= B_ * S_ * T4) return;
    float4 v = x[idx];
    int t4 = idx % T4;
    int bs = idx / T4;
    int s  = bs % S_;
    int b  = bs / S_;
    int tb = t4 * 4;
    if (v.x != 0.0f) { int c = atomicAdd(&g_cnt[b * T_ + tb + 0], 1); if (c < CAP_) g_list[(b * T_ + tb + 0) * CAP_ + c] = (unsigned short)s; }
    if (v.y != 0.0f) { int c = atomicAdd(&g_cnt[b * T_ + tb + 1], 1); if (c < CAP_) g_list[(b * T_ + tb + 1) * CAP_ + c] = (unsigned short)s; }
    if (v.z != 0.0f) { int c = atomicAdd(&g_cnt[b * T_ + tb + 2], 1); if (c < CAP_) g_list[(b * T_ + tb + 2) * CAP_ + c] = (unsigned short)s; }
    if (v.w != 0.0f) { int c = atomicAdd(&g_cnt[b * T_ + tb + 3], 1); if (c < CAP_) g_list[(b * T_ + tb + 3) * CAP_ + c] = (unsigned short)s; }
}

// ---------------------------------------------------------------------------
// smem layout (bytes)
#define OFF_OH   0                      // u32 [SP_][32] one-hot weights           101376
#define OFF_POT  101376                 // u16 [NT_][PSTR_]                         34816
#define OFF_Z2   136192                 // uint2 [NT_][ZSTR_]                       17152
#define OFF_SL   153344                 // u16 [TC_][CAP_] staged lists             16384
#define OFF_CNT  169728                 // i32 [T_]                                  2000
#define OFF_TL   171728                 // u32 [KS_]                                   84
#define OFF_TH   171812                 // u32 [KS_]                                   84
#define OFF_TK   171896                 // u32 ticket                                   8
#define SMEM_TOTAL 171904

__global__ void __launch_bounds__(THREADS_, 1) pot_kernel(const int* __restrict__ table) {
    extern __shared__ unsigned char smem[];
    unsigned*       oh     = (unsigned*)(smem + OFF_OH);
    unsigned short* pot_sm = (unsigned short*)(smem + OFF_POT);
    uint2*          z2     = (uint2*)(smem + OFF_Z2);
    uint4*          sl4    = (uint4*)(smem + OFF_SL);
    int*            cnt_sm = (int*)(smem + OFF_CNT);
    unsigned*       TLs    = (unsigned*)(smem + OFF_TL);
    unsigned*       THs    = (unsigned*)(smem + OFF_TH);
    unsigned*       tick   = (unsigned*)(smem + OFF_TK);

    const int tid = threadIdx.x;
    const int warpid = tid >> 5, lane = tid & 31;
    const int tl = tid & 31, n2 = tid >> 5;           // phase-2 mapping

    // Table (time-flipped input): orig[v][j] = table[v][KS_-1-j]; per-j byte columns.
    if (tid < KS_) {
        int j = tid;
        unsigned lo = 0, hi = 0;
#pragma unroll
        for (int v = 0; v < 4; v++) lo |= ((unsigned)table[v * KS_ + (KS_ - 1 - j)]) << (8 * v);
#pragma unroll
        for (int v = 4; v < 8; v++) hi |= ((unsigned)table[v * KS_ + (KS_ - 1 - j)]) << (8 * (v - 4));
        TLs[j] = lo; THs[j] = hi;
    }

    for (;;) {
        if (tid == 0) *tick = atomicAdd(&g_ticket, 1u);
        __syncthreads();
        unsigned my = *tick;
        if (my >= NTICK_) break;
        const int b  = (int)(my >> 4);
        const int n0 = (int)(my & 15u) * NT_;

        // Stage OH tile: oh[s*32+n] = g_oh[s*512 + n0 + n]; sentinel rows = 1 (v=0).
        {
            const uint4 one = make_uint4(1u, 1u, 1u, 1u);
            for (int i = tid; i < SP_ * 8; i += THREADS_) {
                int s = i >> 3, q = i & 7;
                uint4 v;
                if (s < S_) v = *(const uint4*)&g_oh[s * N_ + n0 + 4 * q];
                else        v = one;
                ((uint4*)oh)[i] = v;
            }
        }
        for (int i = tid; i < T_; i += THREADS_) {
            int c = g_cnt[b * T_ + i];
            cnt_sm[i] = c < CAP_ ? c : CAP_;
        }
        for (int i = tid; i < NT_ * PSTR_ / 2; i += THREADS_) ((unsigned*)pot_sm)[i] = 0u;
        __syncthreads();

        for (int c0 = 0; c0 < T_; c0 += TC_) {
            const int TCcur = (c0 + TC_ < T_) ? TC_ : (T_ - c0);   // 64 or 52

            // Stage spike lists (tails already sentinel in global).
            {
                const uint4* gl4 = (const uint4*)&g_list[(size_t)(b * T_ + c0) * CAP_];
                for (int i = tid; i < TCcur * 16; i += THREADS_) {
                    int ti = i >> 4, vq = i & 15;
                    if (vq * 8 < cnt_sm[c0 + ti]) sl4[i] = gl4[i];
                }
            }
            __syncthreads();

            // ---- Phase 1: warp = one tau x 32 neurons. Uniform s -> conflict-free
            // 128B row LDS; 1 LDS + 1 IADD per neuron-spike.
#pragma unroll
            for (int p = 0; p < 2; p++) {
                int ti = p * 32 + warpid;
                if (ti < TCcur) {
                    int cnt = cnt_sm[c0 + ti];
                    const uint4* lp4 = &sl4[ti * 16];
                    unsigned zL = 0u, zH = 0u;
                    for (int cb = 0; cb < cnt; cb += 8) {
                        uint4 v4 = lp4[cb >> 3];
                        unsigned z32 = 0u;
                        z32 += oh[(v4.x & 0xFFFFu) * 32 + lane];
                        z32 += oh[(v4.x >> 16)     * 32 + lane];
                        z32 += oh[(v4.y & 0xFFFFu) * 32 + lane];
                        z32 += oh[(v4.y >> 16)     * 32 + lane];
                        z32 += oh[(v4.z & 0xFFFFu) * 32 + lane];
                        z32 += oh[(v4.z >> 16)     * 32 + lane];
                        z32 += oh[(v4.w & 0xFFFFu) * 32 + lane];
                        z32 += oh[(v4.w >> 16)     * 32 + lane];
                        unsigned a_ = z32 & 0x0F0F0F0Fu;
                        unsigned b_ = (z32 >> 4) & 0x0F0F0F0Fu;
                        zL += __byte_perm(a_, b_, 0x5140);   // counts v0..v3
                        zH += __byte_perm(a_, b_, 0x7362);   // counts v4..v7
                    }
                    z2[lane * ZSTR_ + ti] = make_uint2(zL, zH);
                }
            }
            __syncthreads();

            // ---- Phase 2: thread owns (n2, t_local = 1+3*tl+k, k<3). j = k+q-2.
            {
                const uint2* zrow = &z2[n2 * ZSTR_];
                int acc0 = 0, acc1 = 0, acc2 = 0;
#pragma unroll
                for (int q = 0; q < 23; q++) {
                    int ti = 3 * tl + 2 - q;
                    bool ok = (unsigned)ti < (unsigned)TCcur;
                    uint2 zz = ok ? zrow[ti] : make_uint2(0u, 0u);
                    {
                        int j = q - 2;                       // k = 0
                        if (j >= 0 && j <= 20) { acc0 = dp4a_(zz.x, TLs[j], acc0); acc0 = dp4a_(zz.y, THs[j], acc0); }
                    }
                    {
                        int j = q - 1;                       // k = 1
                        if (j >= 0 && j <= 20) { acc1 = dp4a_(zz.x, TLs[j], acc1); acc1 = dp4a_(zz.y, THs[j], acc1); }
                    }
                    {
                        int j = q;                           // k = 2
                        if (j <= 20) { acc2 = dp4a_(zz.x, TLs[j], acc2); acc2 = dp4a_(zz.y, THs[j], acc2); }
                    }
                }
                unsigned short* p = &pot_sm[n2 * PSTR_ + c0 + 1 + 3 * tl];
                p[0] = (unsigned short)(p[0] + acc0);
                p[1] = (unsigned short)(p[1] + acc1);
                p[2] = (unsigned short)(p[2] + acc2);
            }
            __syncthreads();
        }

        // ---- Fused per-(b,t) argmax over this tile -> packed atomicMax.
        for (int t = tid; t < TP_; t += THREADS_) {
            int bv = -1, bn = 0;
#pragma unroll
            for (int nn = 0; nn < NT_; nn++) {
                int v = pot_sm[nn * PSTR_ + t];
                if (v > bv) { bv = v; bn = nn; }
            }
            unsigned key = ((unsigned)bv << 10) | (unsigned)(511 - (n0 + bn));
            atomicMax(&g_key[b * TP_ + t], key);
        }
        __syncthreads();
    }
}

// ---------------------------------------------------------------------------
__global__ void __launch_bounds__(32) scan_kernel(float* __restrict__ out) {
    __shared__ unsigned skey[TP_];
    __shared__ unsigned bm[17];
    int b = blockIdx.x;
    int lane = threadIdx.x;
#pragma unroll
    for (int w = 0; w < 17; w++) {
        int t = w * 32 + lane;
        unsigned key = (t < TP_) ? g_key[b * TP_ + t] : 0u;
        if (t < TP_) skey[t] = key;
        unsigned m = __ballot_sync(0xffffffffu, (int)(key >> 10) > THETA_);
        if (lane == 0) bm[w] = m;
    }
    __syncwarp();
    if (lane == 0) {
        int t = 0;
        while (t < TP_) {
            int w = t >> 5;
            unsigned m = bm[w] & (0xffffffffu << (t & 31));
            while (m == 0u && ++w < 17) m = bm[w];
            if (m == 0u) break;
            int t2 = (w << 5) + __ffs(m) - 1;
            if (t2 >= TP_) break;
            int n = 511 - (int)(skey[t2] & 1023u);
            out[((size_t)b * N_ + n) * TP_ + t2] = 1.0f;
            t = t2 + KS_ + 1;
        }
    }
}

// ---------------------------------------------------------------------------
extern "C" void kernel_launch(void* const* d_in, const int* in_sizes, int n_in,
                              void* d_out, int out_size) {
    const float* x      = (const float*)d_in[0];
    const int*   weight = (const int*)d_in[1];
    const int*   table  = (const int*)d_in[2];
    float*       out    = (float*)d_out;

    cudaFuncSetAttribute(pot_kernel, cudaFuncAttributeMaxDynamicSharedMemorySize, SMEM_TOTAL);

    cudaMemsetAsync(out, 0, (size_t)out_size * sizeof(float), 0);               // 1
    fill_kernel<<<(B_ * T_ * CAP_ / 8 + 255) / 256, 256>>>();                   // 2
    oh_kernel<<<(N_ * S_ + 255) / 256, 256>>>(weight);                          // 3
    prepass_kernel<<<(B_ * S_ * (T_ / 4) + 255) / 256, 256>>>((const float4*)x);// 4

    pot_kernel<<<GRID_, THREADS_, SMEM_TOTAL>>>(table);                         // 5 -> profiled

    scan_kernel<<<B_, 32>>>(out);                                               // 6
}

// round 9
// speedup vs baseline: 1.0243x; 1.0243x over previous
#include <cuda_runtime.h>
#include <cstdint>
#include <cstddef>

#define B_      64
#define S_      784
#define SP_     792      // padded synapse rows (sentinel w=0)
#define T_      500
#define N_      512
#define TP_     522
#define KS_     21
#define THETA_  40
#define CAP_    128
#define NT_     32
#define TC_     128      // tau chunk
#define THREADS_ 1024
#define GRID_   148
#define PSTR_   544      // u16 pot row stride
#define ZSTR_   130      // uint2 z row stride
#define NTICK_  (B_ * (N_ / NT_))     // 1024

__device__ int            g_cnt[B_ * T_];
__device__ unsigned short g_list[B_ * T_ * CAP_];   // sentinel-filled (s=784)
__device__ unsigned       g_key[B_ * TP_];
__device__ unsigned       g_wp[S_ * (N_ / 4)];      // byte-packed weights (w<<2), 4 n/word
__device__ unsigned       g_ticket;

__device__ __forceinline__ int dp4a_(unsigned a, unsigned b, int c) {
    int r;
    asm("dp4a.u32.u32 %0, %1, %2, %3;" : "=r"(r) : "r"(a), "r"(b), "r"(c));
    return r;
}

// ---------------------------------------------------------------------------
__global__ void fill_kernel() {
    int i = blockIdx.x * blockDim.x + threadIdx.x;
    const int L4 = B_ * T_ * CAP_ / 8;
    if (i < L4) {
        uint4 v; v.x = v.y = v.z = v.w = 0x03100310u;
        ((uint4*)g_list)[i] = v;
    }
    if (i < B_ * T_)  g_cnt[i] = 0;
    if (i < B_ * TP_) g_key[i] = 0u;
    if (i == 0)       g_ticket = 0u;
}

// Pack weights: g_wp[s*128 + ng] byte m = w[4ng+m][s] << 2.
__global__ void wp_kernel(const int* __restrict__ weight) {
    int i = blockIdx.x * blockDim.x + threadIdx.x;   // ng-major, s fastest
    if (i >= (N_ / 4) * S_) return;
    int ng = i / S_, s = i - ng * S_;
    unsigned word = 0;
#pragma unroll
    for (int m = 0; m < 4; m++)
        word |= (((unsigned)(weight[(4 * ng + m) * S_ + s] & 7)) << 2) << (8 * m);
    g_wp[s * (N_ / 4) + ng] = word;
}

__global__ void prepass_kernel(const float4* __restrict__ x) {
    const int T4 = T_ / 4;
    int idx = blockIdx.x * blockDim.x + threadIdx.x;
    if (idx >= B_ * S_ * T4) return;
    float4 v = x[idx];
    int t4 = idx % T4;
    int bs = idx / T4;
    int s  = bs % S_;
    int b  = bs / S_;
    int tb = t4 * 4;
    if (v.x != 0.0f) { int c = atomicAdd(&g_cnt[b * T_ + tb + 0], 1); if (c < CAP_) g_list[(b * T_ + tb + 0) * CAP_ + c] = (unsigned short)s; }
    if (v.y != 0.0f) { int c = atomicAdd(&g_cnt[b * T_ + tb + 1], 1); if (c < CAP_) g_list[(b * T_ + tb + 1) * CAP_ + c] = (unsigned short)s; }
    if (v.z != 0.0f) { int c = atomicAdd(&g_cnt[b * T_ + tb + 2], 1); if (c < CAP_) g_list[(b * T_ + tb + 2) * CAP_ + c] = (unsigned short)s; }
    if (v.w != 0.0f) { int c = atomicAdd(&g_cnt[b * T_ + tb + 3], 1); if (c < CAP_) g_list[(b * T_ + tb + 3) * CAP_ + c] = (unsigned short)s; }
}

// ---------------------------------------------------------------------------
// smem layout (bytes)
#define OFF_WP   0                      // u32 [SP_][4 replicas][8]                101376
#define OFF_POT  101376                 // u16 [NT_][PSTR_]                         34816
#define OFF_Z2   136192                 // uint2 [NT_][ZSTR_]                       33280
#define OFF_SL   169472                 // u16 [TC_][CAP_]                          32768
#define OFF_CNT  202240                 // i32 [T_]                                  2000
#define OFF_C4   204240                 // i32 [32]                                   128
#define OFF_TLH  204368                 // uint2 [KS_]                                168
#define OFF_TK   204536                 // u32 ticket                                   8
#define SMEM_TOTAL 204544

__global__ void __launch_bounds__(THREADS_, 1) pot_kernel(const int* __restrict__ table) {
    extern __shared__ unsigned char smem[];
    unsigned*       wp32r  = (unsigned*)(smem + OFF_WP);
    unsigned short* pot_sm = (unsigned short*)(smem + OFF_POT);
    uint2*          z2     = (uint2*)(smem + OFF_Z2);
    uint4*          sl4    = (uint4*)(smem + OFF_SL);
    int*            cnt_sm = (int*)(smem + OFF_CNT);
    int*            c4     = (int*)(smem + OFF_C4);
    uint2*          TLH    = (uint2*)(smem + OFF_TLH);
    unsigned*       tick   = (unsigned*)(smem + OFF_TK);

    const int tid = threadIdx.x;
    const int warpid = tid >> 5, lane = tid & 31;
    const int slot = lane >> 3, sub = lane & 7;       // phase-1: tau slot / neuron group
    const int tl = tid & 31, n2 = tid >> 5;           // phase-2: t group / neuron (warp-uniform)

    // Table (time-flipped input): orig[v][j] = table[v][KS_-1-j]; per-j byte columns.
    if (tid < KS_) {
        int j = tid;
        unsigned lo = 0, hi = 0;
#pragma unroll
        for (int v = 0; v < 4; v++) lo |= ((unsigned)table[v * KS_ + (KS_ - 1 - j)]) << (8 * v);
#pragma unroll
        for (int v = 4; v < 8; v++) hi |= ((unsigned)table[v * KS_ + (KS_ - 1 - j)]) << (8 * (v - 4));
        TLH[j] = make_uint2(lo, hi);
    }

    for (;;) {
        if (tid == 0) *tick = atomicAdd(&g_ticket, 1u);
        __syncthreads();                              // also fences smem reuse
        unsigned my = *tick;
        if (my >= NTICK_) break;
        const int b  = (int)(my >> 4);
        const int n0 = (int)(my & 15u) * NT_;

        // Stage weights, 4 bank-replicas: word(s, c, sub) at s*32 + c*8 + sub.
        for (int i = tid; i < SP_ * 8; i += THREADS_) {
            int s = i >> 3, sb = i & 7;
            unsigned word = (s < S_) ? g_wp[s * (N_ / 4) + (n0 >> 2) + sb] : 0u;
#pragma unroll
            for (int c = 0; c < 4; c++) wp32r[s * 32 + c * 8 + sb] = word;
        }
        for (int i = tid; i < T_; i += THREADS_) {
            int c = g_cnt[b * T_ + i];
            cnt_sm[i] = c < CAP_ ? c : CAP_;
        }
        for (int i = tid; i < NT_ * PSTR_ / 2; i += THREADS_) ((unsigned*)pot_sm)[i] = 0u;
        __syncthreads();

        for (int c0 = 0; c0 < T_; c0 += TC_) {
            const int TCcur = (c0 + TC_ < T_) ? TC_ : (T_ - c0);   // 128 or 116

            // Per-warp-group (4 taus) max counts.
            if (tid < 32) {
                int m = 0;
#pragma unroll
                for (int d = 0; d < 4; d++) {
                    int tt = 4 * tid + d;
                    if (tt < TCcur) { int c = cnt_sm[c0 + tt]; m = c > m ? c : m; }
                }
                c4[tid] = m;
            }
            __syncthreads();

            // Stage spike lists up to group max (tails hold sentinel in global).
            {
                const uint4* gl4 = (const uint4*)&g_list[(size_t)(b * T_ + c0) * CAP_];
                for (int i = tid; i < TCcur * 16; i += THREADS_) {
                    int ti = i >> 4, vq = i & 15;
                    if (vq * 8 < c4[ti >> 2]) sl4[i] = gl4[i];
                }
            }
            __syncthreads();

            // ---- Phase 1: warp = 4 taus x 8 lanes x 4 neurons. Replica `slot`
            // keeps every LDS conflict-free regardless of s.
            {
                int ti = (warpid << 2) + slot;
                if (ti < TCcur) {
                    int cnt4v = c4[warpid];
                    const uint4* lp4 = &sl4[ti * 16];
                    const unsigned* wbase = wp32r + (slot << 3) + sub;
                    unsigned zL0 = 0, zL1 = 0, zL2 = 0, zL3 = 0;
                    unsigned zH0 = 0, zH1 = 0, zH2 = 0, zH3 = 0;
                    for (int cb = 0; cb < cnt4v; cb += 8) {
                        uint4 v4 = lp4[cb >> 3];
                        unsigned za = 0, zb = 0, zc = 0, zd = 0;
#define SPIKE_(ss) do { unsigned wsh = wbase[(ss) * 32];                     \
        za += 1u << __byte_perm(wsh, 0u, 0x4440);                            \
        zb += 1u << __byte_perm(wsh, 0u, 0x4441);                            \
        zc += 1u << __byte_perm(wsh, 0u, 0x4442);                            \
        zd += 1u << __byte_perm(wsh, 0u, 0x4443); } while (0)
                        SPIKE_(v4.x & 0xFFFFu); SPIKE_(v4.x >> 16);
                        SPIKE_(v4.y & 0xFFFFu); SPIKE_(v4.y >> 16);
                        SPIKE_(v4.z & 0xFFFFu); SPIKE_(v4.z >> 16);
                        SPIKE_(v4.w & 0xFFFFu); SPIKE_(v4.w >> 16);
#undef SPIKE_
#define EXP_(z, L, H) do { unsigned a_ = (z) & 0x0F0F0F0Fu;                  \
        unsigned b_ = ((z) >> 4) & 0x0F0F0F0Fu;                              \
        L += __byte_perm(a_, b_, 0x5140); H += __byte_perm(a_, b_, 0x7362); } while (0)
                        EXP_(za, zL0, zH0); EXP_(zb, zL1, zH1);
                        EXP_(zc, zL2, zH2); EXP_(zd, zL3, zH3);
#undef EXP_
                    }
                    int nb = sub << 2;
                    z2[(nb + 0) * ZSTR_ + ti] = make_uint2(zL0, zH0);
                    z2[(nb + 1) * ZSTR_ + ti] = make_uint2(zL1, zH1);
                    z2[(nb + 2) * ZSTR_ + ti] = make_uint2(zL2, zH2);
                    z2[(nb + 3) * ZSTR_ + ti] = make_uint2(zL3, zH3);
                }
            }
            __syncthreads();

            // ---- Phase 2: sliding-window stencil. Thread owns (n2, 5 t's).
            // t_local = tbase+k, tau_local = tbase+k-1-j; window w0..w4 per j.
            {
                const uint2* zrow = &z2[n2 * ZSTR_];
                const int tbase = 1 + 5 * tl;
                const uint2 zzero = make_uint2(0u, 0u);
#define ZLD(ti_) (((unsigned)(ti_) < (unsigned)TCcur) ? zrow[(ti_)] : zzero)
                int acc0 = 0, acc1 = 0, acc2 = 0, acc3 = 0, acc4 = 0;
                uint2 w0, w1, w2, w3, w4;
                w1 = ZLD(tbase - 21); w2 = ZLD(tbase - 20);
                w3 = ZLD(tbase - 19); w4 = ZLD(tbase - 18);
#pragma unroll
                for (int jj = 0; jj <= 20; jj++) {
                    const int j = 20 - jj;
                    w0 = w1; w1 = w2; w2 = w3; w3 = w4;
                    w4 = ZLD(tbase + 3 - j);
                    uint2 tlh = TLH[j];
                    acc0 = dp4a_(w0.x, tlh.x, acc0); acc0 = dp4a_(w0.y, tlh.y, acc0);
                    acc1 = dp4a_(w1.x, tlh.x, acc1); acc1 = dp4a_(w1.y, tlh.y, acc1);
                    acc2 = dp4a_(w2.x, tlh.x, acc2); acc2 = dp4a_(w2.y, tlh.y, acc2);
                    acc3 = dp4a_(w3.x, tlh.x, acc3); acc3 = dp4a_(w3.y, tlh.y, acc3);
                    acc4 = dp4a_(w4.x, tlh.x, acc4); acc4 = dp4a_(w4.y, tlh.y, acc4);
                }
#undef ZLD
                unsigned short* prow = &pot_sm[n2 * PSTR_ + c0];
                const int lim = TCcur + 20;
                if (tbase     <= lim) prow[tbase    ] = (unsigned short)(prow[tbase    ] + acc0);
                if (tbase + 1 <= lim) prow[tbase + 1] = (unsigned short)(prow[tbase + 1] + acc1);
                if (tbase + 2 <= lim) prow[tbase + 2] = (unsigned short)(prow[tbase + 2] + acc2);
                if (tbase + 3 <= lim) prow[tbase + 3] = (unsigned short)(prow[tbase + 3] + acc3);
                if (tbase + 4 <= lim) prow[tbase + 4] = (unsigned short)(prow[tbase + 4] + acc4);
            }
            __syncthreads();
        }

        // ---- Fused per-(b,t) argmax over this tile -> packed atomicMax.
        for (int t = tid; t < TP_; t += THREADS_) {
            int bv = -1, bn = 0;
#pragma unroll
            for (int nn = 0; nn < NT_; nn++) {
                int v = pot_sm[nn * PSTR_ + t];
                if (v > bv) { bv = v; bn = nn; }
            }
            unsigned key = ((unsigned)bv << 10) | (unsigned)(511 - (n0 + bn));
            atomicMax(&g_key[b * TP_ + t], key);
        }
        __syncthreads();
    }
}

// ---------------------------------------------------------------------------
__global__ void __launch_bounds__(32) scan_kernel(float* __restrict__ out) {
    __shared__ unsigned skey[TP_];
    __shared__ unsigned bm[17];
    int b = blockIdx.x;
    int lane = threadIdx.x;
#pragma unroll
    for (int w = 0; w < 17; w++) {
        int t = w * 32 + lane;
        unsigned key = (t < TP_) ? g_key[b * TP_ + t] : 0u;
        if (t < TP_) skey[t] = key;
        unsigned m = __ballot_sync(0xffffffffu, (int)(key >> 10) > THETA_);
        if (lane == 0) bm[w] = m;
    }
    __syncwarp();
    if (lane == 0) {
        int t = 0;
        while (t < TP_) {
            int w = t >> 5;
            unsigned m = bm[w] & (0xffffffffu << (t & 31));
            while (m == 0u && ++w < 17) m = bm[w];
            if (m == 0u) break;
            int t2 = (w << 5) + __ffs(m) - 1;
            if (t2 >= TP_) break;
            int n = 511 - (int)(skey[t2] & 1023u);
            out[((size_t)b * N_ + n) * TP_ + t2] = 1.0f;
            t = t2 + KS_ + 1;
        }
    }
}

// ---------------------------------------------------------------------------
extern "C" void kernel_launch(void* const* d_in, const int* in_sizes, int n_in,
                              void* d_out, int out_size) {
    const float* x      = (const float*)d_in[0];
    const int*   weight = (const int*)d_in[1];
    const int*   table  = (const int*)d_in[2];
    float*       out    = (float*)d_out;

    cudaFuncSetAttribute(pot_kernel, cudaFuncAttributeMaxDynamicSharedMemorySize, SMEM_TOTAL);

    cudaMemsetAsync(out, 0, (size_t)out_size * sizeof(float), 0);               // 1
    fill_kernel<<<(B_ * T_ * CAP_ / 8 + 255) / 256, 256>>>();                   // 2
    wp_kernel<<<((N_ / 4) * S_ + 255) / 256, 256>>>(weight);                    // 3
    prepass_kernel<<<(B_ * S_ * (T_ / 4) + 255) / 256, 256>>>((const float4*)x);// 4

    pot_kernel<<<GRID_, THREADS_, SMEM_TOTAL>>>(table);                         // 5 -> profiled

    scan_kernel<<<B_, 32>>>(out);                                               // 6
}

// round 10
// speedup vs baseline: 1.1439x; 1.1167x over previous
#include <cuda_runtime.h>
#include <cstdint>
#include <cstddef>

#define B_      64
#define S_      784
#define SP_     792      // padded synapse rows (sentinel w=0)
#define T_      500
#define N_      512
#define TP_     522
#define KS_     21
#define THETA_  40
#define CAP_    128
#define NT_     32
#define TC_     64       // tau chunk
#define NCHUNK_ 8        // ceil(500/64)
#define THREADS_ 512
#define GRID_   296
#define PSTR_   544      // u16 pot row stride
#define ZSTR_   66       // uint2 z row stride
#define WREP_   (SP_ * 8)             // words per weight replica (6336)
#define NTICK_  (B_ * (N_ / NT_))     // 1024

__device__ int            g_cnt[B_ * T_];
__device__ unsigned short g_list[B_ * T_ * CAP_];   // sentinel-filled (s=784)
__device__ unsigned       g_key[B_ * TP_];
__device__ unsigned       g_wp[S_ * (N_ / 4)];      // byte-packed weights (w<<2), 4 n/word
__device__ unsigned       g_ticket;

__device__ __forceinline__ int dp4a_(unsigned a, unsigned b, int c) {
    int r;
    asm("dp4a.u32.u32 %0, %1, %2, %3;" : "=r"(r) : "r"(a), "r"(b), "r"(c));
    return r;
}

// ---------------------------------------------------------------------------
__global__ void fill_kernel() {
    int i = blockIdx.x * blockDim.x + threadIdx.x;
    const int L4 = B_ * T_ * CAP_ / 8;
    if (i < L4) {
        uint4 v; v.x = v.y = v.z = v.w = 0x03100310u;
        ((uint4*)g_list)[i] = v;
    }
    if (i < B_ * T_)  g_cnt[i] = 0;
    if (i < B_ * TP_) g_key[i] = 0u;
    if (i == 0)       g_ticket = 0u;
}

// Pack weights: g_wp[s*128 + ng] byte m = w[4ng+m][s] << 2.
__global__ void wp_kernel(const int* __restrict__ weight) {
    int i = blockIdx.x * blockDim.x + threadIdx.x;
    if (i >= (N_ / 4) * S_) return;
    int ng = i / S_, s = i - ng * S_;
    unsigned word = 0;
#pragma unroll
    for (int m = 0; m < 4; m++)
        word |= (((unsigned)(weight[(4 * ng + m) * S_ + s] & 7)) << 2) << (8 * m);
    g_wp[s * (N_ / 4) + ng] = word;
}

__global__ void prepass_kernel(const float4* __restrict__ x) {
    const int T4 = T_ / 4;
    int idx = blockIdx.x * blockDim.x + threadIdx.x;
    if (idx >= B_ * S_ * T4) return;
    float4 v = x[idx];
    int t4 = idx % T4;
    int bs = idx / T4;
    int s  = bs % S_;
    int b  = bs / S_;
    int tb = t4 * 4;
    if (v.x != 0.0f) { int c = atomicAdd(&g_cnt[b * T_ + tb + 0], 1); if (c < CAP_) g_list[(b * T_ + tb + 0) * CAP_ + c] = (unsigned short)s; }
    if (v.y != 0.0f) { int c = atomicAdd(&g_cnt[b * T_ + tb + 1], 1); if (c < CAP_) g_list[(b * T_ + tb + 1) * CAP_ + c] = (unsigned short)s; }
    if (v.z != 0.0f) { int c = atomicAdd(&g_cnt[b * T_ + tb + 2], 1); if (c < CAP_) g_list[(b * T_ + tb + 2) * CAP_ + c] = (unsigned short)s; }
    if (v.w != 0.0f) { int c = atomicAdd(&g_cnt[b * T_ + tb + 3], 1); if (c < CAP_) g_list[(b * T_ + tb + 3) * CAP_ + c] = (unsigned short)s; }
}

// ---------------------------------------------------------------------------
// smem layout (bytes); total 105,088 -> 2 CTAs/SM
#define OFF_WP   0                      // u32 [2 replicas][SP_][8]                 50688
#define OFF_POT  50688                  // u16 [NT_][PSTR_]                         34816
#define OFF_Z2   85504                  // uint2 [NT_][ZSTR_]                       16896
#define OFF_C4   102400                 // i32 [NCHUNK_][16]                          512
#define OFF_TLH  102912                 // uint2 [KS_]                                168
#define OFF_TK   103080                 // u32 ticket                                   8
#define SMEM_TOTAL 103088

__global__ void __launch_bounds__(THREADS_, 2) pot_kernel(const int* __restrict__ table) {
    extern __shared__ unsigned char smem[];
    unsigned*       wp     = (unsigned*)(smem + OFF_WP);
    unsigned short* pot_sm = (unsigned short*)(smem + OFF_POT);
    uint2*          z2     = (uint2*)(smem + OFF_Z2);
    int*            c4     = (int*)(smem + OFF_C4);
    uint2*          TLH    = (uint2*)(smem + OFF_TLH);
    unsigned*       tick   = (unsigned*)(smem + OFF_TK);

    const int tid = threadIdx.x;
    const int warpid = tid >> 5, lane = tid & 31;     // 16 warps
    const int slot = lane >> 3, sub = lane & 7;       // phase-1: tau slot / word
    const int tl = tid & 15, n2 = tid >> 4;           // phase-2: t group / neuron

    // Table (time-flipped input): orig[v][j] = table[v][KS_-1-j]; per-j byte columns.
    if (tid < KS_) {
        int j = tid;
        unsigned lo = 0, hi = 0;
#pragma unroll
        for (int v = 0; v < 4; v++) lo |= ((unsigned)table[v * KS_ + (KS_ - 1 - j)]) << (8 * v);
#pragma unroll
        for (int v = 4; v < 8; v++) hi |= ((unsigned)table[v * KS_ + (KS_ - 1 - j)]) << (8 * (v - 4));
        TLH[j] = make_uint2(lo, hi);
    }

    for (;;) {
        if (tid == 0) *tick = atomicAdd(&g_ticket, 1u);
        __syncthreads();                              // also fences smem reuse
        unsigned my = *tick;
        if (my >= NTICK_) break;
        const int b  = (int)(my >> 4);
        const int n0 = (int)(my & 15u) * NT_;

        // Stage weights (both replicas).
        for (int i = tid; i < WREP_; i += THREADS_) {
            int s = i >> 3, sb = i & 7;
            unsigned word = (s < S_) ? g_wp[s * (N_ / 4) + (n0 >> 2) + sb] : 0u;
            wp[i] = word;
            wp[WREP_ + i] = word;
        }
        // All per-chunk group maxima (16 groups of 4 taus per chunk).
        for (int i = tid; i < NCHUNK_ * 16; i += THREADS_) {
            int ch = i >> 4, grp = i & 15;
            int m = 0;
#pragma unroll
            for (int d = 0; d < 4; d++) {
                int tt = ch * TC_ + grp * 4 + d;
                if (tt < T_) {
                    int c = g_cnt[b * T_ + tt];
                    c = c < CAP_ ? c : CAP_;
                    m = c > m ? c : m;
                }
            }
            c4[i] = m;
        }
        for (int i = tid; i < NT_ * PSTR_ / 2; i += THREADS_) ((unsigned*)pot_sm)[i] = 0u;
        __syncthreads();

        int ch = 0;
        for (int c0 = 0; c0 < T_; c0 += TC_, ch++) {
            const int TCcur = (c0 + TC_ < T_) ? TC_ : (T_ - c0);   // 64 or 52

            // ---- Phase 1: warp = 4 taus x (8 words x 4 neurons). Replica slot&1;
            // lists via direct LDG (uniform per slot) with prefetch.
            {
                int ti = (warpid << 2) + slot;
                if (ti < TCcur) {
                    int cnt4v = c4[ch * 16 + warpid];
                    const uint4* lp4 = (const uint4*)&g_list[(size_t)(b * T_ + c0 + ti) * CAP_];
                    const unsigned* wbase = wp + (slot & 1) * WREP_ + sub;
                    unsigned zL0 = 0, zL1 = 0, zL2 = 0, zL3 = 0;
                    unsigned zH0 = 0, zH1 = 0, zH2 = 0, zH3 = 0;
                    int iters = (cnt4v + 7) >> 3;
                    uint4 nxt = make_uint4(0x03100310u, 0x03100310u, 0x03100310u, 0x03100310u);
                    if (iters > 0) nxt = __ldg(lp4);
                    for (int it = 0; it < iters; it++) {
                        uint4 v4 = nxt;
                        if (it + 1 < iters) nxt = __ldg(lp4 + it + 1);
                        unsigned za = 0, zb = 0, zc = 0, zd = 0;
#define SPIKE_(ss) do { unsigned wsh = wbase[(ss) * 8];                      \
        za += 1u << __byte_perm(wsh, 0u, 0x4440);                            \
        zb += 1u << __byte_perm(wsh, 0u, 0x4441);                            \
        zc += 1u << __byte_perm(wsh, 0u, 0x4442);                            \
        zd += 1u << __byte_perm(wsh, 0u, 0x4443); } while (0)
                        SPIKE_(v4.x & 0xFFFFu); SPIKE_(v4.x >> 16);
                        SPIKE_(v4.y & 0xFFFFu); SPIKE_(v4.y >> 16);
                        SPIKE_(v4.z & 0xFFFFu); SPIKE_(v4.z >> 16);
                        SPIKE_(v4.w & 0xFFFFu); SPIKE_(v4.w >> 16);
#undef SPIKE_
#define EXP_(z, L, H) do { unsigned a_ = (z) & 0x0F0F0F0Fu;                  \
        unsigned b_ = ((z) >> 4) & 0x0F0F0F0Fu;                              \
        L += __byte_perm(a_, b_, 0x5140); H += __byte_perm(a_, b_, 0x7362); } while (0)
                        EXP_(za, zL0, zH0); EXP_(zb, zL1, zH1);
                        EXP_(zc, zL2, zH2); EXP_(zd, zL3, zH3);
#undef EXP_
                    }
                    int nb = sub << 2;
                    z2[(nb + 0) * ZSTR_ + ti] = make_uint2(zL0, zH0);
                    z2[(nb + 1) * ZSTR_ + ti] = make_uint2(zL1, zH1);
                    z2[(nb + 2) * ZSTR_ + ti] = make_uint2(zL2, zH2);
                    z2[(nb + 3) * ZSTR_ + ti] = make_uint2(zL3, zH3);
                }
            }
            __syncthreads();

            // ---- Phase 2: 6-wide sliding-window stencil. Thread owns (n2, 6 t's).
            {
                const uint2* zrow = &z2[n2 * ZSTR_];
                const int tbase = 1 + 6 * tl;
                const uint2 zzero = make_uint2(0u, 0u);
#define ZLD(ti_) (((unsigned)(ti_) < (unsigned)TCcur) ? zrow[(ti_)] : zzero)
                int acc0 = 0, acc1 = 0, acc2 = 0, acc3 = 0, acc4 = 0, acc5 = 0;
                uint2 w0, w1, w2, w3, w4, w5;
                w1 = ZLD(tbase - 21); w2 = ZLD(tbase - 20); w3 = ZLD(tbase - 19);
                w4 = ZLD(tbase - 18); w5 = ZLD(tbase - 17);
#pragma unroll
                for (int jj = 0; jj <= 20; jj++) {
                    const int j = 20 - jj;
                    w0 = w1; w1 = w2; w2 = w3; w3 = w4; w4 = w5;
                    w5 = ZLD(tbase + 4 - j);
                    uint2 tlh = TLH[j];
                    acc0 = dp4a_(w0.x, tlh.x, acc0); acc0 = dp4a_(w0.y, tlh.y, acc0);
                    acc1 = dp4a_(w1.x, tlh.x, acc1); acc1 = dp4a_(w1.y, tlh.y, acc1);
                    acc2 = dp4a_(w2.x, tlh.x, acc2); acc2 = dp4a_(w2.y, tlh.y, acc2);
                    acc3 = dp4a_(w3.x, tlh.x, acc3); acc3 = dp4a_(w3.y, tlh.y, acc3);
                    acc4 = dp4a_(w4.x, tlh.x, acc4); acc4 = dp4a_(w4.y, tlh.y, acc4);
                    acc5 = dp4a_(w5.x, tlh.x, acc5); acc5 = dp4a_(w5.y, tlh.y, acc5);
                }
#undef ZLD
                unsigned short* prow = &pot_sm[n2 * PSTR_ + c0];
                const int lim = TCcur + 20;
                if (tbase     <= lim) prow[tbase    ] = (unsigned short)(prow[tbase    ] + acc0);
                if (tbase + 1 <= lim) prow[tbase + 1] = (unsigned short)(prow[tbase + 1] + acc1);
                if (tbase + 2 <= lim) prow[tbase + 2] = (unsigned short)(prow[tbase + 2] + acc2);
                if (tbase + 3 <= lim) prow[tbase + 3] = (unsigned short)(prow[tbase + 3] + acc3);
                if (tbase + 4 <= lim) prow[tbase + 4] = (unsigned short)(prow[tbase + 4] + acc4);
                if (tbase + 5 <= lim) prow[tbase + 5] = (unsigned short)(prow[tbase + 5] + acc5);
            }
            __syncthreads();
        }

        // ---- Fused per-(b,t) argmax over this tile -> packed atomicMax.
        for (int t = tid; t < TP_; t += THREADS_) {
            int bv = -1, bn = 0;
#pragma unroll
            for (int nn = 0; nn < NT_; nn++) {
                int v = pot_sm[nn * PSTR_ + t];
                if (v > bv) { bv = v; bn = nn; }
            }
            unsigned key = ((unsigned)bv << 10) | (unsigned)(511 - (n0 + bn));
            atomicMax(&g_key[b * TP_ + t], key);
        }
        __syncthreads();
    }
}

// ---------------------------------------------------------------------------
__global__ void __launch_bounds__(32) scan_kernel(float* __restrict__ out) {
    __shared__ unsigned skey[TP_];
    __shared__ unsigned bm[17];
    int b = blockIdx.x;
    int lane = threadIdx.x;
#pragma unroll
    for (int w = 0; w < 17; w++) {
        int t = w * 32 + lane;
        unsigned key = (t < TP_) ? g_key[b * TP_ + t] : 0u;
        if (t < TP_) skey[t] = key;
        unsigned m = __ballot_sync(0xffffffffu, (int)(key >> 10) > THETA_);
        if (lane == 0) bm[w] = m;
    }
    __syncwarp();
    if (lane == 0) {
        int t = 0;
        while (t < TP_) {
            int w = t >> 5;
            unsigned m = bm[w] & (0xffffffffu << (t & 31));
            while (m == 0u && ++w < 17) m = bm[w];
            if (m == 0u) break;
            int t2 = (w << 5) + __ffs(m) - 1;
            if (t2 >= TP_) break;
            int n = 511 - (int)(skey[t2] & 1023u);
            out[((size_t)b * N_ + n) * TP_ + t2] = 1.0f;
            t = t2 + KS_ + 1;
        }
    }
}

// ---------------------------------------------------------------------------
extern "C" void kernel_launch(void* const* d_in, const int* in_sizes, int n_in,
                              void* d_out, int out_size) {
    const float* x      = (const float*)d_in[0];
    const int*   weight = (const int*)d_in[1];
    const int*   table  = (const int*)d_in[2];
    float*       out    = (float*)d_out;

    cudaFuncSetAttribute(pot_kernel, cudaFuncAttributeMaxDynamicSharedMemorySize, SMEM_TOTAL);

    cudaMemsetAsync(out, 0, (size_t)out_size * sizeof(float), 0);               // 1
    fill_kernel<<<(B_ * T_ * CAP_ / 8 + 255) / 256, 256>>>();                   // 2
    wp_kernel<<<((N_ / 4) * S_ + 255) / 256, 256>>>(weight);                    // 3
    prepass_kernel<<<(B_ * S_ * (T_ / 4) + 255) / 256, 256>>>((const float4*)x);// 4

    pot_kernel<<<GRID_, THREADS_, SMEM_TOTAL>>>(table);                         // 5 -> profiled

    scan_kernel<<<B_, 32>>>(out);                                               // 6
}

// round 11
// speedup vs baseline: 1.2888x; 1.1266x over previous
#include <cuda_runtime.h>
#include <cstdint>
#include <cstddef>

#define B_      64
#define S_      784
#define SP_     792      // padded synapse rows (sentinel oh=0)
#define T_      500
#define N_      512
#define TP_     522
#define KS_     21
#define THETA_  40
#define CAP_    128
#define NT_     32
#define TC_     128      // tau chunk
#define NCHUNK_ 4
#define THREADS_ 1024
#define GRID_   148
#define PSTR_   544      // u16 pot row stride
#define ZSTR_   130      // uint2 z row stride
#define NTICK_  (B_ * (N_ / NT_))     // 1024

__device__ int            g_cnt[B_ * T_];
__device__ unsigned short g_list[B_ * T_ * CAP_];   // sentinel-filled (s=784)
__device__ unsigned       g_key[B_ * TP_];
__device__ unsigned       g_oh[S_ * N_];            // one-hot nibble words (v-1 encoding)
__device__ unsigned       g_ticket;

__device__ __forceinline__ int dp4a_(unsigned a, unsigned b, int c) {
    int r;
    asm("dp4a.u32.u32 %0, %1, %2, %3;" : "=r"(r) : "r"(a), "r"(b), "r"(c));
    return r;
}

// ---------------------------------------------------------------------------
__global__ void fill_kernel() {
    int i = blockIdx.x * blockDim.x + threadIdx.x;
    const int L4 = B_ * T_ * CAP_ / 8;
    if (i < L4) {
        uint4 v; v.x = v.y = v.z = v.w = 0x03100310u;
        ((uint4*)g_list)[i] = v;
    }
    if (i < B_ * T_)  g_cnt[i] = 0;
    if (i < B_ * TP_) g_key[i] = 0u;
    if (i == 0)       g_ticket = 0u;
}

// One-hot weights, value-0 dropped: g_oh[s*N+n] = w ? 1<<(4*(w-1)) : 0.
__global__ void oh_kernel(const int* __restrict__ weight) {
    int i = blockIdx.x * blockDim.x + threadIdx.x;
    if (i >= N_ * S_) return;
    int n = i / S_, s = i - n * S_;
    int w = weight[i] & 7;
    g_oh[s * N_ + n] = w ? (1u << (4 * (w - 1))) : 0u;
}

__global__ void prepass_kernel(const float4* __restrict__ x) {
    const int T4 = T_ / 4;
    int idx = blockIdx.x * blockDim.x + threadIdx.x;
    if (idx >= B_ * S_ * T4) return;
    float4 v = x[idx];
    int t4 = idx % T4;
    int bs = idx / T4;
    int s  = bs % S_;
    int b  = bs / S_;
    int tb = t4 * 4;
    if (v.x != 0.0f) { int c = atomicAdd(&g_cnt[b * T_ + tb + 0], 1); if (c < CAP_) g_list[(b * T_ + tb + 0) * CAP_ + c] = (unsigned short)s; }
    if (v.y != 0.0f) { int c = atomicAdd(&g_cnt[b * T_ + tb + 1], 1); if (c < CAP_) g_list[(b * T_ + tb + 1) * CAP_ + c] = (unsigned short)s; }
    if (v.z != 0.0f) { int c = atomicAdd(&g_cnt[b * T_ + tb + 2], 1); if (c < CAP_) g_list[(b * T_ + tb + 2) * CAP_ + c] = (unsigned short)s; }
    if (v.w != 0.0f) { int c = atomicAdd(&g_cnt[b * T_ + tb + 3], 1); if (c < CAP_) g_list[(b * T_ + tb + 3) * CAP_ + c] = (unsigned short)s; }
}

// ---------------------------------------------------------------------------
// smem layout (bytes); total ~170KB -> 1 CTA/SM
#define OFF_OH   0                      // u32 [SP_][32] one-hot tile             101376
#define OFF_POT  101376                 // u16 [NT_][PSTR_]                        34816
#define OFF_Z2   136192                 // uint2 [NT_][ZSTR_]                      33280
#define OFF_C4   169472                 // i32 [NCHUNK_][32]                         512
#define OFF_TLH  169984                 // uint2 [KS_]                               168
#define OFF_TK   170152                 // u32 ticket                                  8
#define SMEM_TOTAL 170160

__global__ void __launch_bounds__(THREADS_, 1) pot_kernel(const int* __restrict__ table) {
    extern __shared__ unsigned char smem[];
    unsigned*       oh     = (unsigned*)(smem + OFF_OH);
    unsigned short* pot_sm = (unsigned short*)(smem + OFF_POT);
    uint2*          z2     = (uint2*)(smem + OFF_Z2);
    int*            c4     = (int*)(smem + OFF_C4);
    uint2*          TLH    = (uint2*)(smem + OFF_TLH);
    unsigned*       tick   = (unsigned*)(smem + OFF_TK);

    const int tid = threadIdx.x;
    const int warpid = tid >> 5, lane = tid & 31;     // 32 warps
    const int slot = lane >> 3, sub = lane & 7;       // phase-1: tau slot / neuron quad
    const int tl = tid & 31, n2 = tid >> 5;           // phase-2: t group / neuron

    // Table (time-flipped input): orig[v][j] = table[v][KS_-1-j].
    // v-1 packing: TLH.x bytes = orig[1..4][j], TLH.y bytes = orig[5..7][j], 0.
    if (tid < KS_) {
        int j = tid;
        unsigned lo = 0, hi = 0;
#pragma unroll
        for (int v = 1; v <= 4; v++) lo |= ((unsigned)table[v * KS_ + (KS_ - 1 - j)]) << (8 * (v - 1));
#pragma unroll
        for (int v = 5; v <= 7; v++) hi |= ((unsigned)table[v * KS_ + (KS_ - 1 - j)]) << (8 * (v - 5));
        TLH[j] = make_uint2(lo, hi);
    }

    for (;;) {
        if (tid == 0) *tick = atomicAdd(&g_ticket, 1u);
        __syncthreads();                              // also fences smem reuse
        unsigned my = *tick;
        if (my >= NTICK_) break;
        const int b  = (int)(my >> 4);
        const int n0 = (int)(my & 15u) * NT_;

        // Stage one-hot tile: oh[s*32 + n] = g_oh[s*512 + n0 + n]; sentinel rows 0.
        for (int i = tid; i < SP_ * 8; i += THREADS_) {
            int s = i >> 3, q = i & 7;
            uint4 v = make_uint4(0u, 0u, 0u, 0u);
            if (s < S_) v = *(const uint4*)&g_oh[s * N_ + n0 + 4 * q];
            ((uint4*)oh)[i] = v;
        }
        // Per-chunk group maxima (32 groups of 4 taus per chunk).
        for (int i = tid; i < NCHUNK_ * 32; i += THREADS_) {
            int ch = i >> 5, grp = i & 31;
            int m = 0;
#pragma unroll
            for (int d = 0; d < 4; d++) {
                int tt = ch * TC_ + grp * 4 + d;
                if (tt < T_) {
                    int c = g_cnt[b * T_ + tt];
                    c = c < CAP_ ? c : CAP_;
                    m = c > m ? c : m;
                }
            }
            c4[i] = m;
        }
        for (int i = tid; i < NT_ * PSTR_ / 2; i += THREADS_) ((unsigned*)pot_sm)[i] = 0u;
        __syncthreads();

        int ch = 0;
        for (int c0 = 0; c0 < T_; c0 += TC_, ch++) {
            const int TCcur = (c0 + TC_ < T_) ? TC_ : (T_ - c0);   // 128 or 116

            // ---- Phase 1: warp = 4 taus; lane (slot,sub) serves 4 neurons via
            // one LDS.128 of the one-hot tile per spike. Conflict-free: each
            // 8-lane phase reads one contiguous 128B row.
            {
                int ti = (warpid << 2) + slot;
                if (ti < TCcur) {
                    int cnt4v = c4[(ch << 5) + warpid];
                    const uint4* lp4 = (const uint4*)&g_list[(size_t)(b * T_ + c0 + ti) * CAP_];
                    const unsigned* ohb = oh + (sub << 2);
                    unsigned zL0 = 0, zL1 = 0, zL2 = 0, zL3 = 0;
                    unsigned zH0 = 0, zH1 = 0, zH2 = 0, zH3 = 0;
                    int iters = (cnt4v + 7) >> 3;
                    uint4 nxt = make_uint4(0x03100310u, 0x03100310u, 0x03100310u, 0x03100310u);
                    if (iters > 0) nxt = __ldg(lp4);
                    for (int it = 0; it < iters; it++) {
                        uint4 v4 = nxt;
                        if (it + 1 < iters) nxt = __ldg(lp4 + it + 1);
                        unsigned za = 0, zb = 0, zc = 0, zd = 0;
#define SPIKE_(ss) do { uint4 o_ = *(const uint4*)(ohb + (ss) * 32);         \
        za += o_.x; zb += o_.y; zc += o_.z; zd += o_.w; } while (0)
                        SPIKE_(v4.x & 0xFFFFu); SPIKE_(v4.x >> 16);
                        SPIKE_(v4.y & 0xFFFFu); SPIKE_(v4.y >> 16);
                        SPIKE_(v4.z & 0xFFFFu); SPIKE_(v4.z >> 16);
                        SPIKE_(v4.w & 0xFFFFu); SPIKE_(v4.w >> 16);
#undef SPIKE_
                        // Expand nibble counts (v1..v7) to byte pairs.
#define EXP_(z, L, H) do { unsigned a_ = (z) & 0x0F0F0F0Fu;                  \
        unsigned b_ = ((z) >> 4) & 0x0F0F0F0Fu;                              \
        L += __byte_perm(a_, b_, 0x5140); H += __byte_perm(a_, b_, 0x7362); } while (0)
                        EXP_(za, zL0, zH0); EXP_(zb, zL1, zH1);
                        EXP_(zc, zL2, zH2); EXP_(zd, zL3, zH3);
#undef EXP_
                    }
                    int nb = sub << 2;
                    z2[(nb + 0) * ZSTR_ + ti] = make_uint2(zL0, zH0);
                    z2[(nb + 1) * ZSTR_ + ti] = make_uint2(zL1, zH1);
                    z2[(nb + 2) * ZSTR_ + ti] = make_uint2(zL2, zH2);
                    z2[(nb + 3) * ZSTR_ + ti] = make_uint2(zL3, zH3);
                }
            }
            __syncthreads();

            // ---- Phase 2: 5-wide sliding-window stencil. Thread owns (n2, 5 t's).
            {
                const uint2* zrow = &z2[n2 * ZSTR_];
                const int tbase = 1 + 5 * tl;
                const uint2 zzero = make_uint2(0u, 0u);
#define ZLD(ti_) (((unsigned)(ti_) < (unsigned)TCcur) ? zrow[(ti_)] : zzero)
                int acc0 = 0, acc1 = 0, acc2 = 0, acc3 = 0, acc4 = 0;
                uint2 w0, w1, w2, w3, w4;
                w1 = ZLD(tbase - 21); w2 = ZLD(tbase - 20);
                w3 = ZLD(tbase - 19); w4 = ZLD(tbase - 18);
#pragma unroll
                for (int jj = 0; jj <= 20; jj++) {
                    const int j = 20 - jj;
                    w0 = w1; w1 = w2; w2 = w3; w3 = w4;
                    w4 = ZLD(tbase + 3 - j);
                    uint2 tlh = TLH[j];
                    acc0 = dp4a_(w0.x, tlh.x, acc0); acc0 = dp4a_(w0.y, tlh.y, acc0);
                    acc1 = dp4a_(w1.x, tlh.x, acc1); acc1 = dp4a_(w1.y, tlh.y, acc1);
                    acc2 = dp4a_(w2.x, tlh.x, acc2); acc2 = dp4a_(w2.y, tlh.y, acc2);
                    acc3 = dp4a_(w3.x, tlh.x, acc3); acc3 = dp4a_(w3.y, tlh.y, acc3);
                    acc4 = dp4a_(w4.x, tlh.x, acc4); acc4 = dp4a_(w4.y, tlh.y, acc4);
                }
#undef ZLD
                unsigned short* prow = &pot_sm[n2 * PSTR_ + c0];
                const int lim = TCcur + 20;
                if (tbase     <= lim) prow[tbase    ] = (unsigned short)(prow[tbase    ] + acc0);
                if (tbase + 1 <= lim) prow[tbase + 1] = (unsigned short)(prow[tbase + 1] + acc1);
                if (tbase + 2 <= lim) prow[tbase + 2] = (unsigned short)(prow[tbase + 2] + acc2);
                if (tbase + 3 <= lim) prow[tbase + 3] = (unsigned short)(prow[tbase + 3] + acc3);
                if (tbase + 4 <= lim) prow[tbase + 4] = (unsigned short)(prow[tbase + 4] + acc4);
            }
            __syncthreads();
        }

        // ---- Fused per-(b,t) argmax over this tile -> packed atomicMax.
        for (int t = tid; t < TP_; t += THREADS_) {
            int bv = -1, bn = 0;
#pragma unroll
            for (int nn = 0; nn < NT_; nn++) {
                int v = pot_sm[nn * PSTR_ + t];
                if (v > bv) { bv = v; bn = nn; }
            }
            unsigned key = ((unsigned)bv << 10) | (unsigned)(511 - (n0 + bn));
            atomicMax(&g_key[b * TP_ + t], key);
        }
        __syncthreads();
    }
}

// ---------------------------------------------------------------------------
__global__ void __launch_bounds__(32) scan_kernel(float* __restrict__ out) {
    __shared__ unsigned skey[TP_];
    __shared__ unsigned bm[17];
    int b = blockIdx.x;
    int lane = threadIdx.x;
#pragma unroll
    for (int w = 0; w < 17; w++) {
        int t = w * 32 + lane;
        unsigned key = (t < TP_) ? g_key[b * TP_ + t] : 0u;
        if (t < TP_) skey[t] = key;
        unsigned m = __ballot_sync(0xffffffffu, (int)(key >> 10) > THETA_);
        if (lane == 0) bm[w] = m;
    }
    __syncwarp();
    if (lane == 0) {
        int t = 0;
        while (t < TP_) {
            int w = t >> 5;
            unsigned m = bm[w] & (0xffffffffu << (t & 31));
            while (m == 0u && ++w < 17) m = bm[w];
            if (m == 0u) break;
            int t2 = (w << 5) + __ffs(m) - 1;
            if (t2 >= TP_) break;
            int n = 511 - (int)(skey[t2] & 1023u);
            out[((size_t)b * N_ + n) * TP_ + t2] = 1.0f;
            t = t2 + KS_ + 1;
        }
    }
}

// ---------------------------------------------------------------------------
extern "C" void kernel_launch(void* const* d_in, const int* in_sizes, int n_in,
                              void* d_out, int out_size) {
    const float* x      = (const float*)d_in[0];
    const int*   weight = (const int*)d_in[1];
    const int*   table  = (const int*)d_in[2];
    float*       out    = (float*)d_out;

    cudaFuncSetAttribute(pot_kernel, cudaFuncAttributeMaxDynamicSharedMemorySize, SMEM_TOTAL);

    cudaMemsetAsync(out, 0, (size_t)out_size * sizeof(float), 0);               // 1
    fill_kernel<<<(B_ * T_ * CAP_ / 8 + 255) / 256, 256>>>();                   // 2
    oh_kernel<<<(N_ * S_ + 255) / 256, 256>>>(weight);                          // 3
    prepass_kernel<<<(B_ * S_ * (T_ / 4) + 255) / 256, 256>>>((const float4*)x);// 4

    pot_kernel<<<GRID_, THREADS_, SMEM_TOTAL>>>(table);                         // 5 -> profiled

    scan_kernel<<<B_, 32>>>(out);                                               // 6
}